// round 11
// baseline (speedup 1.0000x reference)
#include <cuda_runtime.h>
#include <cstdint>

// Unfold (im2col): x[32,64,64,64] f32, 3x3/s1 -> out[32,576,3844] f32
// out[(bc*9+3ki+kj)][l+e] = ch[ki*64 + kj + (l+e) + 2*floor((l+e)/62)]
//
// R10 core (pitch-33 padded smem, conflict-free stride-4 gather; per (m,ki)
// the 12 elements come from the 8-word window C..C+7, row-crossing folded
// via 6 SELs; 8 LDS + 6 SEL + 3 st.global.cs.v4 per (m,ki)).
// R11 delta: persistent 296-CTA grid, double-buffered smem, next channel
// prefetched into registers (2x LDG.128/thread) while the current channel is
// computed -> per-channel stage latency fully hidden; stage bubbles drop
// 2048 -> 296 and the wave-quantization tail disappears.

#define HW    64
#define CH    4096
#define WO    62
#define L     3844
#define NV4   961             // float4 per output row
#define SMW   4240            // 4096 + pad + slack for C+7 overread
#define NT    512
#define NCH   2048
#define GRID  296             // 148 SMs x 2 resident CTAs

__device__ __forceinline__ int PADI(int w) { return w + (w >> 5); }

__device__ __forceinline__ void stcs4(float4* p, float4 v) {
    asm volatile("st.global.cs.v4.f32 [%0], {%1,%2,%3,%4};"
                 :: "l"(p), "f"(v.x), "f"(v.y), "f"(v.z), "f"(v.w)
                 : "memory");
}

// scatter this thread's 2 float4s into the padded buffer
__device__ __forceinline__ void store_pad(float* buf, int tid,
                                          float4 a0, float4 a1)
{
    int w0 = 4 * tid;
    buf[PADI(w0 + 0)] = a0.x;
    buf[PADI(w0 + 1)] = a0.y;
    buf[PADI(w0 + 2)] = a0.z;
    buf[PADI(w0 + 3)] = a0.w;
    int w1 = 4 * (tid + NT);
    buf[PADI(w1 + 0)] = a1.x;
    buf[PADI(w1 + 1)] = a1.y;
    buf[PADI(w1 + 2)] = a1.z;
    buf[PADI(w1 + 3)] = a1.w;
}

// emit the 9 output rows of one channel from padded smem (R10 body)
__device__ __forceinline__ void emit_channel(const float* __restrict__ sm,
                                             float4* __restrict__ dst4,
                                             int tid)
{
#pragma unroll
    for (int it = 0; it < 2; ++it) {          // 961 = 512 + 449
        const int m = tid + NT * it;
        if (m < NV4) {
            const int l   = 4 * m;
            const int i0  = l / WO;           // const divisor -> mulhi
            const int j0  = l - WO * i0;
            const int b0  = l + 2 * i0;
            const bool cr = (j0 == 60);       // only e=2,3 cross (+2 words)

#pragma unroll
            for (int ki = 0; ki < 3; ++ki) {
                const int C = ki * HW + b0;

                const float s0 = sm[PADI(C + 0)];
                const float s1 = sm[PADI(C + 1)];
                const float s2 = sm[PADI(C + 2)];
                const float s3 = sm[PADI(C + 3)];
                const float s4 = sm[PADI(C + 4)];
                const float s5 = sm[PADI(C + 5)];
                const float s6 = sm[PADI(C + 6)];
                const float s7 = sm[PADI(C + 7)];

                float4 v;
                v.x = s0; v.y = s1;
                v.z = cr ? s4 : s2; v.w = cr ? s5 : s3;
                stcs4(&dst4[(3 * ki + 0) * NV4 + m], v);
                v.x = s1; v.y = s2;
                v.z = cr ? s5 : s3; v.w = cr ? s6 : s4;
                stcs4(&dst4[(3 * ki + 1) * NV4 + m], v);
                v.x = s2; v.y = s3;
                v.z = cr ? s6 : s4; v.w = cr ? s7 : s5;
                stcs4(&dst4[(3 * ki + 2) * NV4 + m], v);
            }
        }
    }
}

__global__ __launch_bounds__(NT, 2)
void unfold_kernel(const float* __restrict__ x, float* __restrict__ out)
{
    __shared__ float sm[2][SMW];

    const int tid = threadIdx.x;
    int c = blockIdx.x;                        // first channel for this CTA

    // prime the pipeline: channel c -> regs -> buf 0
    float4 a0, a1;
    {
        const float4* __restrict__ s4 =
            reinterpret_cast<const float4*>(x + (size_t)c * CH);
        a0 = s4[tid];
        a1 = s4[tid + NT];
    }
    store_pad(sm[0], tid, a0, a1);
    __syncthreads();

    int p = 0;
    for (;;) {
        const int nextc = c + GRID;
        const bool has_next = (nextc < NCH);
        if (has_next) {                        // issue prefetch LDGs early;
            const float4* __restrict__ s4 =    // latency hides under emit
                reinterpret_cast<const float4*>(x + (size_t)nextc * CH);
            a0 = s4[tid];
            a1 = s4[tid + NT];
        }

        emit_channel(sm[p],
                     reinterpret_cast<float4*>(out) + (size_t)c * 9 * NV4,
                     tid);

        if (!has_next) break;
        store_pad(sm[1 - p], tid, a0, a1);     // other buffer: no read hazard
        __syncthreads();                       // orders buffer reuse
        p ^= 1;
        c = nextc;
    }
}

extern "C" void kernel_launch(void* const* d_in, const int* in_sizes, int n_in,
                              void* d_out, int out_size)
{
    const float* x = (const float*)d_in[0];
    float* out = (float*)d_out;

    unfold_kernel<<<GRID, NT>>>(x, out);       // persistent: all CTAs resident
}

// round 12
// speedup vs baseline: 1.0975x; 1.0975x over previous
#include <cuda_runtime.h>
#include <cstdint>

// Unfold (im2col): x[32,64,64,64] f32, 3x3/s1 -> out[32,576,3844] f32
// out[(bc*9+3ki+kj)][l+e] = ch[ki*64 + kj + (l+e) + 2*floor((l+e)/62)]
//
// R10 core: block = one channel staged in pitch-33 padded smem (conflict-free
// stride-4 gather). Per (m,ki) the 12 elements (kj=0..2, e=0..3) come from
// the 8-word window C..C+7; row-crossing folds in via 6 SELs.
// 8 LDS + 6 SEL + 3 st.global.cs.v4 per (m,ki); 512-thread blocks.
// R12 delta: __launch_bounds__(512, 3) -> regs capped ~42, 3 resident
// CTAs/SM (48 warps) so one CTA's stage/sync bubble overlaps two others'
// store phases.

#define HW    64
#define CH    4096
#define WO    62
#define L     3844
#define NV4   961             // float4 per output row
#define SMW   4240            // 4096 + pad + slack for C+7 overread
#define NT    512

__device__ __forceinline__ int PADI(int w) { return w + (w >> 5); }

__device__ __forceinline__ void stcs4(float4* p, float4 v) {
    asm volatile("st.global.cs.v4.f32 [%0], {%1,%2,%3,%4};"
                 :: "l"(p), "f"(v.x), "f"(v.y), "f"(v.z), "f"(v.w)
                 : "memory");
}

__global__ __launch_bounds__(NT, 3)
void unfold_kernel(const float* __restrict__ x, float* __restrict__ out)
{
    __shared__ float sm[SMW];

    const int bc  = blockIdx.x;               // 0..2047
    const int tid = threadIdx.x;

    // ---- stage channel into padded smem (2 LDG.128 / thread) ----
    {
        const float4* __restrict__ s4 =
            reinterpret_cast<const float4*>(x + (size_t)bc * CH);
#pragma unroll
        for (int v = tid; v < CH / 4; v += NT) {
            float4 d = s4[v];
            int w = 4 * v;
            sm[PADI(w + 0)] = d.x;
            sm[PADI(w + 1)] = d.y;
            sm[PADI(w + 2)] = d.z;
            sm[PADI(w + 3)] = d.w;
        }
    }
    __syncthreads();

    float4* __restrict__ dst4 =
        reinterpret_cast<float4*>(out + (size_t)bc * 9 * L);

    // 961 = 512 + 449
#pragma unroll
    for (int it = 0; it < 2; ++it) {
        const int m = tid + NT * it;
        if (m < NV4) {
            const int l   = 4 * m;
            const int i0  = l / WO;           // const divisor -> mulhi
            const int j0  = l - WO * i0;
            const int b0  = l + 2 * i0;
            const bool cr = (j0 == 60);       // only e=2,3 cross (+2 words)

#pragma unroll
            for (int ki = 0; ki < 3; ++ki) {
                const int C = ki * HW + b0;

                const float s0 = sm[PADI(C + 0)];
                const float s1 = sm[PADI(C + 1)];
                const float s2 = sm[PADI(C + 2)];
                const float s3 = sm[PADI(C + 3)];
                const float s4 = sm[PADI(C + 4)];
                const float s5 = sm[PADI(C + 5)];
                const float s6 = sm[PADI(C + 6)];
                const float s7 = sm[PADI(C + 7)];

                float4 v;
                // kj = 0
                v.x = s0; v.y = s1;
                v.z = cr ? s4 : s2; v.w = cr ? s5 : s3;
                stcs4(&dst4[(3 * ki + 0) * NV4 + m], v);
                // kj = 1
                v.x = s1; v.y = s2;
                v.z = cr ? s5 : s3; v.w = cr ? s6 : s4;
                stcs4(&dst4[(3 * ki + 1) * NV4 + m], v);
                // kj = 2
                v.x = s2; v.y = s3;
                v.z = cr ? s6 : s4; v.w = cr ? s7 : s5;
                stcs4(&dst4[(3 * ki + 2) * NV4 + m], v);
            }
        }
    }
}

extern "C" void kernel_launch(void* const* d_in, const int* in_sizes, int n_in,
                              void* d_out, int out_size)
{
    const float* x = (const float*)d_in[0];
    float* out = (float*)d_out;

    unfold_kernel<<<2048, NT>>>(x, out);      // one block per (b,c) channel
}